// round 9
// baseline (speedup 1.0000x reference)
#include <cuda_runtime.h>
#include <math.h>
#include <stdint.h>

#define Bq 1024
#define Nn 50
#define Hh 128
#define Tt 50
#define Gg 4
#define FULLMASK 0xffffffffu

// Scratch (allocation-free rule: __device__ globals)
__device__ float g_ctx[Bq * Nn * Hh];
__device__ float g_eg [Bq * Nn * Hh];
__device__ float g_ep [Bq * Nn * Hh];
__device__ float g_xw [(size_t)Bq * Nn * 512];  // context @ Wi, PACKED: row*512 + jj*4 + gate
__device__ float g_xw0[512];                    // dec_init @ Wi, packed same way
__device__ float g_Whp[128 * 512];              // packed Wh: [k][jj] -> float4(i,f,g,o cols of jj)

__device__ __forceinline__ float my_tanh(float x) {
    float e = __expf(2.0f * x);
    return 1.0f - __fdividef(2.0f, e + 1.0f);
}
__device__ __forceinline__ float my_sig(float x) {
    return __fdividef(1.0f, 1.0f + __expf(-x));
}
// group barrier: 256 threads, ids 1 and 2
#define GBAR(id) asm volatile("bar.sync %0, 256;" :: "r"(id) : "memory")

// Register-blocked GEMM pass over the 64-row context tile in smem.
// pack_gate: if >=0, outputs go to row*LDO + jj*4 + pack_gate (i|f|g|o interleave).
__device__ __forceinline__ void pre_gemm(
    const float* __restrict__ W, int LD, int coloff,
    const float (*sctx)[128], int rbase, int jj, int row0,
    float* out, int LDO, int pack_gate)
{
    float acc[16];
    #pragma unroll
    for (int r = 0; r < 16; r++) acc[r] = 0.f;
    for (int k4 = 0; k4 < 32; k4++) {
        float w0 = W[(4 * k4 + 0) * LD + coloff + jj];
        float w1 = W[(4 * k4 + 1) * LD + coloff + jj];
        float w2 = W[(4 * k4 + 2) * LD + coloff + jj];
        float w3 = W[(4 * k4 + 3) * LD + coloff + jj];
        #pragma unroll
        for (int r = 0; r < 16; r++) {
            float4 c = reinterpret_cast<const float4*>(&sctx[rbase + r][0])[k4];
            acc[r] = fmaf(w0, c.x, fmaf(w1, c.y, fmaf(w2, c.z, fmaf(w3, c.w, acc[r]))));
        }
    }
    #pragma unroll
    for (int r = 0; r < 16; r++) {
        size_t idx = (pack_gate >= 0)
            ? (size_t)(row0 + rbase + r) * LDO + jj * 4 + pack_gate
            : (size_t)(row0 + rbase + r) * LDO + coloff + jj;
        out[idx] = acc[r];
    }
}

// ---------------- Phase A: context, e_g, e_p, ctx@Wi (packed), Wh pack ----------------
__global__ __launch_bounds__(512) void k_pre(
    const float* __restrict__ pnt, const float* __restrict__ Wemb,
    const float* __restrict__ bemb, const float* __restrict__ Wrg,
    const float* __restrict__ Wrp, const float* __restrict__ Wi,
    const float* __restrict__ Wh, const float* __restrict__ dini)
{
    int nb = (Bq * Nn) / 64;
    if (blockIdx.x == nb) {
        // dec_init @ Wi, packed store
        int j = threadIdx.x;
        float s = 0.f;
        #pragma unroll 4
        for (int k = 0; k < 128; k++) s = fmaf(dini[k], Wi[k * 512 + j], s);
        g_xw0[(j & 127) * 4 + (j >> 7)] = s;
        return;
    }
    if (blockIdx.x == nb + 1) {
        // pack Wh: Whp[k][jj] = (Wh[k][jj], Wh[k][jj+128], Wh[k][jj+256], Wh[k][jj+384])
        for (int i = threadIdx.x; i < 128 * 128; i += 512) {
            int k = i >> 7, jj = i & 127;
            float4 w;
            w.x = Wh[k * 512 + jj];
            w.y = Wh[k * 512 + 128 + jj];
            w.z = Wh[k * 512 + 256 + jj];
            w.w = Wh[k * 512 + 384 + jj];
            reinterpret_cast<float4*>(g_Whp)[i] = w;
        }
        return;
    }
    __shared__ __align__(16) float sctx[64][128];
    int row0 = blockIdx.x * 64;
    int tid = threadIdx.x;
    for (int i = tid; i < 64 * 128; i += 512) {
        int r = i >> 7, h = i & 127;
        int row = row0 + r;
        float px = pnt[row * 2 + 0], py = pnt[row * 2 + 1];
        float v = fmaf(px, Wemb[h], fmaf(py, Wemb[128 + h], bemb[h]));
        sctx[r][h] = v;
        g_ctx[(size_t)row * 128 + h] = v;
    }
    __syncthreads();
    int jj = tid & 127;
    int quarter = tid >> 7;
    int rbase = quarter * 16;

    pre_gemm(Wrg, 128, 0,   sctx, rbase, jj, row0, g_eg, 128, -1);
    pre_gemm(Wrp, 128, 0,   sctx, rbase, jj, row0, g_ep, 128, -1);
    pre_gemm(Wi,  512, 0,   sctx, rbase, jj, row0, g_xw, 512, 0);
    pre_gemm(Wi,  512, 128, sctx, rbase, jj, row0, g_xw, 512, 1);
    pre_gemm(Wi,  512, 256, sctx, rbase, jj, row0, g_xw, 512, 2);
    pre_gemm(Wi,  512, 384, sctx, rbase, jj, row0, g_xw, 512, 3);
}

// ---------------- Phase B+C: T-loop; 2 CTAs/SM x 2 named-barrier groups ----------------
__global__ __launch_bounds__(512, 2) void k_main(
    const float* __restrict__ pnt,
    const float* __restrict__ bl,
    const float* __restrict__ Wqg, const float* __restrict__ vg,
    const float* __restrict__ Wqp, const float* __restrict__ vp,
    const float* __restrict__ Wrc, const float* __restrict__ W1,
    const float* __restrict__ b1, const float* __restrict__ W2,
    const float* __restrict__ b2, float* __restrict__ out)
{
    int b0 = blockIdx.x * Gg;
    int tid = threadIdx.x;
    int lane = tid & 31, wid = tid >> 5;   // 16 warps
    int jj = tid & 127;
    int bq = tid >> 7;                     // 0..3 : batch id within CTA
    int group = tid >> 8;                  // 0..1 : independent 256-thread group
    int gwid = wid & 7;                    // warp id within group
    int gbar = 1 + group;

    __shared__ __align__(16) float sh_h[2][Gg][128];           // ping-pong h
    __shared__ __align__(16) float sh_q[Gg][128], sh_q2[Gg][128];
    __shared__ float sh_u[Gg][52], sh_mask[Gg][52];
    __shared__ __align__(16) float sh_vg[128], sh_vp[128];
    __shared__ int   sh_act[Gg];
    __shared__ float sh_px[Gg], sh_py[Gg], sh_fx[Gg], sh_fy[Gg], sh_R[Gg];

    {   // init (512 threads == Gg*128 exactly)
        sh_h[0][bq][jj] = 0.f; sh_h[1][bq][jj] = 0.f;
        if (tid < Gg * 52) sh_mask[tid / 52][tid % 52] = 0.f;
        if (tid < 128) { sh_vg[tid] = vg[tid]; sh_vp[tid] = vp[tid]; }
        if (tid < Gg) sh_R[tid] = 0.f;
    }
    __syncthreads();

    float* oR  = out;
    float* oV  = out + Bq;
    float* oLP = out + 2 * Bq;
    float* oA  = oLP + (size_t)Bq * Tt * Nn;
    float* oC  = oA  + (size_t)Bq * Tt;
    float* oP  = oC  + (size_t)Bq * Tt * 2;

    const float4* Whp4 = reinterpret_cast<const float4*>(g_Whp);

    // per-thread persistent LSTM cell state c[bq][jj]
    float c_reg = 0.f;
    float4 blv = make_float4(bl[jj], bl[128 + jj], bl[256 + jj], bl[384 + jj]);

    for (int t = 0; t < Tt; t++) {
        int cur = t & 1, nxt = cur ^ 1;
        // ---- F0: fused gates GEMM + LSTM pointwise.
        // Full-CTA barrier aligns both groups so their Whp streams overlap in L1
        // (4 threads per jj read the same line -> L1 dedup -> 1x unique traffic/CTA).
        __syncthreads();
        {
            const float4* xw4 = (t == 0)
                ? reinterpret_cast<const float4*>(g_xw0)
                : reinterpret_cast<const float4*>(g_xw + ((size_t)(b0 + bq) * Nn + sh_act[bq]) * 512);
            float4 acc = xw4[jj];
            #pragma unroll 4
            for (int k = 0; k < 128; k++) {
                float4 w = Whp4[k * 128 + jj];
                float hk = sh_h[cur][bq][k];
                acc.x = fmaf(w.x, hk, acc.x);
                acc.y = fmaf(w.y, hk, acc.y);
                acc.z = fmaf(w.z, hk, acc.z);
                acc.w = fmaf(w.w, hk, acc.w);
            }
            float gi = acc.x + blv.x;
            float gf = acc.y + blv.y;
            float gg = acc.z + blv.z;
            float go = acc.w + blv.w;
            float c2 = my_sig(gf) * c_reg + my_sig(gi) * my_tanh(gg);
            c_reg = c2;
            sh_h[nxt][bq][jj] = my_sig(go) * my_tanh(c2);
        }
        GBAR(gbar);
        // ---- F1: q = h2 @ Wq_g (thread = (bq, jj), split accumulators)
        {
            float qa = 0.f, qb = 0.f;
            #pragma unroll 4
            for (int k = 0; k < 128; k += 2) {
                qa = fmaf(Wqg[k * 128 + jj],       sh_h[nxt][bq][k],     qa);
                qb = fmaf(Wqg[(k + 1) * 128 + jj], sh_h[nxt][bq][k + 1], qb);
            }
            sh_q[bq][jj] = qa + qb;
        }
        GBAR(gbar);
        // ---- F2: u[b,n] = sum_h tanh(e_g+q)*v_g - 1e9*mask (group: 100 rows / 8 warps)
        for (int r = gwid; r < 2 * Nn; r += 8) {
            int b = group * 2 + (r >= Nn); int n = (r >= Nn) ? r - Nn : r;
            const float4* eg4 = reinterpret_cast<const float4*>(
                g_eg + ((size_t)(b0 + b) * Nn + n) * 128);
            float4 e = eg4[lane];
            float4 q = reinterpret_cast<const float4*>(sh_q[b])[lane];
            float4 v = reinterpret_cast<const float4*>(sh_vg)[lane];
            float s = my_tanh(e.x + q.x) * v.x;
            s = fmaf(my_tanh(e.y + q.y), v.y, s);
            s = fmaf(my_tanh(e.z + q.z), v.z, s);
            s = fmaf(my_tanh(e.w + q.w), v.w, s);
            #pragma unroll
            for (int o = 16; o; o >>= 1) s += __shfl_xor_sync(FULLMASK, s, o);
            if (lane == 0) sh_u[b][n] = s - 1e9f * sh_mask[b][n];
        }
        GBAR(gbar);
        // ---- F3: softmax(u) -> p (group warp 0/1 handles its batch)
        if (gwid < 2) {
            int b = group * 2 + gwid;
            float l0 = sh_u[b][lane];
            float l1 = (lane < 18) ? sh_u[b][lane + 32] : -1e38f;
            float m = fmaxf(l0, l1);
            #pragma unroll
            for (int o = 16; o; o >>= 1) m = fmaxf(m, __shfl_xor_sync(FULLMASK, m, o));
            float e0 = __expf(l0 - m);
            float e1 = (lane < 18) ? __expf(l1 - m) : 0.f;
            float s = e0 + e1;
            #pragma unroll
            for (int o = 16; o; o >>= 1) s += __shfl_xor_sync(FULLMASK, s, o);
            float inv = __fdividef(1.f, s);
            sh_u[b][lane] = e0 * inv;
            if (lane < 18) sh_u[b][lane + 32] = e1 * inv;
        }
        GBAR(gbar);
        // ---- F4: glimpse g = p @ e_g -> sh_q
        {
            const float* ep = g_eg + ((size_t)(b0 + bq) * Nn) * 128 + jj;
            float ga = 0.f, gb2 = 0.f;
            #pragma unroll 2
            for (int n = 0; n < Nn; n += 2) {
                ga  = fmaf(sh_u[bq][n],     ep[n * 128],       ga);
                gb2 = fmaf(sh_u[bq][n + 1], ep[(n + 1) * 128], gb2);
            }
            sh_q[bq][jj] = ga + gb2;
        }
        GBAR(gbar);
        // ---- F5: q2 = g @ Wq_p
        {
            float qa = 0.f, qb = 0.f;
            #pragma unroll 4
            for (int k = 0; k < 128; k += 2) {
                qa = fmaf(Wqp[k * 128 + jj],       sh_q[bq][k],     qa);
                qb = fmaf(Wqp[(k + 1) * 128 + jj], sh_q[bq][k + 1], qb);
            }
            sh_q2[bq][jj] = qa + qb;
        }
        GBAR(gbar);
        // ---- F6: logit = 10*tanh(u2) - 1e9*mask
        for (int r = gwid; r < 2 * Nn; r += 8) {
            int b = group * 2 + (r >= Nn); int n = (r >= Nn) ? r - Nn : r;
            const float4* ep4 = reinterpret_cast<const float4*>(
                g_ep + ((size_t)(b0 + b) * Nn + n) * 128);
            float4 e = ep4[lane];
            float4 q = reinterpret_cast<const float4*>(sh_q2[b])[lane];
            float4 v = reinterpret_cast<const float4*>(sh_vp)[lane];
            float s = my_tanh(e.x + q.x) * v.x;
            s = fmaf(my_tanh(e.y + q.y), v.y, s);
            s = fmaf(my_tanh(e.z + q.z), v.z, s);
            s = fmaf(my_tanh(e.w + q.w), v.w, s);
            #pragma unroll
            for (int o = 16; o; o >>= 1) s += __shfl_xor_sync(FULLMASK, s, o);
            if (lane == 0) sh_u[b][n] = 10.0f * my_tanh(s) - 1e9f * sh_mask[b][n];
        }
        GBAR(gbar);
        // ---- F7: log_softmax / softmax / argmax / outputs / state
        if (gwid < 2) {
            int b = group * 2 + gwid; int gb = b0 + b;
            float l0 = sh_u[b][lane];
            float l1 = (lane < 18) ? sh_u[b][lane + 32] : -1e38f;
            float m = fmaxf(l0, l1);
            #pragma unroll
            for (int o = 16; o; o >>= 1) m = fmaxf(m, __shfl_xor_sync(FULLMASK, m, o));
            float e0 = __expf(l0 - m);
            float e1 = (lane < 18) ? __expf(l1 - m) : 0.f;
            float s = e0 + e1;
            #pragma unroll
            for (int o = 16; o; o >>= 1) s += __shfl_xor_sync(FULLMASK, s, o);
            float lgs = logf(s);
            float p0 = e0 / s;
            float p1 = e1 / s;
            size_t base = ((size_t)gb * Tt + t) * Nn;
            oLP[base + lane] = (l0 - m) - lgs;
            oP [base + lane] = p0;
            if (lane < 18) {
                oLP[base + lane + 32] = (l1 - m) - lgs;
                oP [base + lane + 32] = p1;
            }
            float bv = p0; int bi = lane;
            if (lane < 18 && p1 > bv) { bv = p1; bi = lane + 32; }
            #pragma unroll
            for (int o = 16; o; o >>= 1) {
                float ov = __shfl_down_sync(FULLMASK, bv, o);
                int   oi = __shfl_down_sync(FULLMASK, bi, o);
                if (ov > bv || (ov == bv && oi < bi)) { bv = ov; bi = oi; }
            }
            if (lane == 0) {
                int a = bi;
                sh_act[b] = a;
                sh_mask[b][a] = 1.0f;
                oA[(size_t)gb * Tt + t] = (float)a;
                float cx = pnt[((size_t)gb * Nn + a) * 2 + 0];
                float cy = pnt[((size_t)gb * Nn + a) * 2 + 1];
                oC[((size_t)gb * Tt + t) * 2 + 0] = cx;
                oC[((size_t)gb * Tt + t) * 2 + 1] = cy;
                if (t == 0) { sh_fx[b] = cx; sh_fy[b] = cy; }
                else {
                    float dx = cx - sh_px[b], dy = cy - sh_py[b];
                    sh_R[b] += sqrtf(dx * dx + dy * dy + 1e-10f);
                }
                sh_px[b] = cx; sh_py[b] = cy;
            }
        }
        GBAR(gbar);
    } // t loop

    __syncthreads();
    // ---- R closing edge
    if (tid < Gg) {
        int b = tid; int gb = b0 + b;
        float dx = sh_fx[b] - sh_px[b], dy = sh_fy[b] - sh_py[b];
        oR[gb] = sh_R[b] + sqrtf(dx * dx + dy * dy + 1e-10f);
    }
    // ---- dec_last = context[b, last action]  (reuse sh_h[0])
    sh_h[0][bq][jj] = g_ctx[((size_t)(b0 + bq) * Nn + sh_act[bq]) * 128 + jj];
    __syncthreads();
    // ---- critic shortcut: hy = dec_last @ Wref_c (softmax over length-1 enc == 1)
    {
        float ha = 0.f, hb = 0.f;
        #pragma unroll 4
        for (int k = 0; k < 128; k += 2) {
            ha = fmaf(Wrc[k * 128 + jj],       sh_h[0][bq][k],     ha);
            hb = fmaf(Wrc[(k + 1) * 128 + jj], sh_h[0][bq][k + 1], hb);
        }
        sh_q[bq][jj] = ha + hb;
    }
    __syncthreads();
    {
        float za = 0.f, zb = 0.f;
        #pragma unroll 4
        for (int k = 0; k < 128; k += 2) {
            za = fmaf(W1[k * 128 + jj],       sh_q[bq][k],     za);
            zb = fmaf(W1[(k + 1) * 128 + jj], sh_q[bq][k + 1], zb);
        }
        sh_q2[bq][jj] = fmaxf(za + zb + b1[jj], 0.f);
    }
    __syncthreads();
    if (wid < Gg) {
        int b = wid; int gb = b0 + b;
        float4 zq = reinterpret_cast<const float4*>(sh_q2[b])[lane];
        float4 w2 = reinterpret_cast<const float4*>(W2)[lane];
        float s = zq.x * w2.x + zq.y * w2.y + zq.z * w2.z + zq.w * w2.w;
        #pragma unroll
        for (int o = 16; o; o >>= 1) s += __shfl_xor_sync(FULLMASK, s, o);
        if (lane == 0) oV[gb] = s + b2[0];
    }
}

extern "C" void kernel_launch(void* const* d_in, const int* in_sizes, int n_in,
                              void* d_out, int out_size) {
    const float* pnt  = (const float*)d_in[0];
    const float* Wemb = (const float*)d_in[1];
    const float* bemb = (const float*)d_in[2];
    const float* dini = (const float*)d_in[3];
    const float* Wi   = (const float*)d_in[4];
    const float* Wh   = (const float*)d_in[5];
    const float* bl   = (const float*)d_in[6];
    const float* Wqg  = (const float*)d_in[7];
    const float* Wrg  = (const float*)d_in[8];
    const float* vg   = (const float*)d_in[9];
    const float* Wqp  = (const float*)d_in[10];
    const float* Wrp  = (const float*)d_in[11];
    const float* vp   = (const float*)d_in[12];
    // d_in[13..16]: Wi_c, Wh_c, b_c, Wq_c — dead (softmax over length-1 enc)
    const float* Wrc  = (const float*)d_in[17];
    // d_in[18]: v_c — dead
    const float* W1   = (const float*)d_in[19];
    const float* b1   = (const float*)d_in[20];
    const float* W2   = (const float*)d_in[21];
    const float* b2   = (const float*)d_in[22];

    k_pre<<<(Bq * Nn) / 64 + 2, 512>>>(pnt, Wemb, bemb, Wrg, Wrp, Wi, Wh, dini);
    k_main<<<Bq / Gg, 512>>>(pnt, bl, Wqg, vg, Wqp, vp,
                             Wrc, W1, b1, W2, b2, (float*)d_out);
}

// round 10
// speedup vs baseline: 1.1792x; 1.1792x over previous
#include <cuda_runtime.h>
#include <math.h>
#include <stdint.h>

#define Bq 1024
#define Nn 50
#define Hh 128
#define Tt 50
#define Gg 2
#define FULLMASK 0xffffffffu

// Scratch (allocation-free rule: __device__ globals)
__device__ float g_ctx[Bq * Nn * Hh];
__device__ float g_eg [Bq * Nn * Hh];
__device__ float g_ep [Bq * Nn * Hh];
__device__ float g_xw [(size_t)Bq * Nn * 512];  // context @ Wi
__device__ float g_xw0[512];                    // dec_init @ Wi

__device__ __forceinline__ float my_tanh(float x) {
    float e = __expf(2.0f * x);
    return 1.0f - __fdividef(2.0f, e + 1.0f);
}
__device__ __forceinline__ float my_sig(float x) {
    return __fdividef(1.0f, 1.0f + __expf(-x));
}

// Merged register-blocked GEMM: two weight-column chunks share each sctx load.
__device__ __forceinline__ void pre_gemm2(
    const float* __restrict__ Wa, int LDa, int cola, float* outA, int LDOa,
    const float* __restrict__ Wb, int LDb, int colb, float* outB, int LDOb,
    const float (*sctx)[128], int rbase, int jj, int row0)
{
    float accA[16], accB[16];
    #pragma unroll
    for (int r = 0; r < 16; r++) { accA[r] = 0.f; accB[r] = 0.f; }
    for (int k4 = 0; k4 < 32; k4++) {
        float wa0 = Wa[(4 * k4 + 0) * LDa + cola + jj];
        float wa1 = Wa[(4 * k4 + 1) * LDa + cola + jj];
        float wa2 = Wa[(4 * k4 + 2) * LDa + cola + jj];
        float wa3 = Wa[(4 * k4 + 3) * LDa + cola + jj];
        float wb0 = Wb[(4 * k4 + 0) * LDb + colb + jj];
        float wb1 = Wb[(4 * k4 + 1) * LDb + colb + jj];
        float wb2 = Wb[(4 * k4 + 2) * LDb + colb + jj];
        float wb3 = Wb[(4 * k4 + 3) * LDb + colb + jj];
        #pragma unroll
        for (int r = 0; r < 16; r++) {
            float4 c = reinterpret_cast<const float4*>(&sctx[rbase + r][0])[k4];
            accA[r] = fmaf(wa0, c.x, fmaf(wa1, c.y, fmaf(wa2, c.z, fmaf(wa3, c.w, accA[r]))));
            accB[r] = fmaf(wb0, c.x, fmaf(wb1, c.y, fmaf(wb2, c.z, fmaf(wb3, c.w, accB[r]))));
        }
    }
    #pragma unroll
    for (int r = 0; r < 16; r++) {
        outA[(size_t)(row0 + rbase + r) * LDOa + cola + jj] = accA[r];
        outB[(size_t)(row0 + rbase + r) * LDOb + colb + jj] = accB[r];
    }
}

// ---------------- Phase A: context, e_g, e_p, ctx@Wi ----------------
__global__ __launch_bounds__(512) void k_pre(
    const float* __restrict__ pnt, const float* __restrict__ Wemb,
    const float* __restrict__ bemb, const float* __restrict__ Wrg,
    const float* __restrict__ Wrp, const float* __restrict__ Wi,
    const float* __restrict__ dini)
{
    if (blockIdx.x == (Bq * Nn) / 64) {
        int j = threadIdx.x;
        float s = 0.f;
        #pragma unroll 4
        for (int k = 0; k < 128; k++) s = fmaf(dini[k], Wi[k * 512 + j], s);
        g_xw0[j] = s;
        return;
    }
    __shared__ __align__(16) float sctx[64][128];
    int row0 = blockIdx.x * 64;
    int tid = threadIdx.x;
    for (int i = tid; i < 64 * 128; i += 512) {
        int r = i >> 7, h = i & 127;
        int row = row0 + r;
        float px = pnt[row * 2 + 0], py = pnt[row * 2 + 1];
        float v = fmaf(px, Wemb[h], fmaf(py, Wemb[128 + h], bemb[h]));
        sctx[r][h] = v;
        g_ctx[(size_t)row * 128 + h] = v;
    }
    __syncthreads();
    int jj = tid & 127;
    int quarter = tid >> 7;
    int rbase = quarter * 16;

    pre_gemm2(Wrg, 128, 0,   g_eg, 128,  Wrp, 128, 0,   g_ep, 128, sctx, rbase, jj, row0);
    pre_gemm2(Wi,  512, 0,   g_xw, 512,  Wi,  512, 128, g_xw, 512, sctx, rbase, jj, row0);
    pre_gemm2(Wi,  512, 256, g_xw, 512,  Wi,  512, 384, g_xw, 512, sctx, rbase, jj, row0);
}

// ---------------- Phase B+C: full T-loop, 4 CTAs/SM ----------------
__global__ __launch_bounds__(256, 4) void k_main(
    const float* __restrict__ pnt, const float* __restrict__ Wh,
    const float* __restrict__ bl,
    const float* __restrict__ Wqg, const float* __restrict__ vg,
    const float* __restrict__ Wqp, const float* __restrict__ vp,
    const float* __restrict__ Wrc, const float* __restrict__ W1,
    const float* __restrict__ b1, const float* __restrict__ W2,
    const float* __restrict__ b2, float* __restrict__ out)
{
    int b0 = blockIdx.x * Gg;
    int tid = threadIdx.x;
    int lane = tid & 31, wid = tid >> 5;   // 8 warps
    int jj = tid & 127;
    int half = tid >> 7;                   // 0..1 : k-half (gates) / batch id (others)

    __shared__ __align__(16) float4 sh_part[2][Gg][128];        // 8 KB gates partials
    __shared__ __align__(16) float sh_h[Gg][128], sh_c[Gg][128];
    __shared__ __align__(16) float sh_q[Gg][128], sh_q2[Gg][128];
    __shared__ float sh_u[Gg][52], sh_mask[Gg][52];
    __shared__ __align__(16) float sh_vg[128], sh_vp[128];
    __shared__ int   sh_act[Gg];
    __shared__ float sh_px[Gg], sh_py[Gg], sh_fx[Gg], sh_fy[Gg], sh_R[Gg];

    {   // init (256 threads == Gg*128 exactly)
        sh_h[half][jj] = 0.f; sh_c[half][jj] = 0.f;
        if (tid < Gg * 52) sh_mask[tid / 52][tid % 52] = 0.f;
        if (tid < 128) { sh_vg[tid] = vg[tid]; sh_vp[tid] = vp[tid]; }
        if (tid < Gg) sh_R[tid] = 0.f;
    }
    __syncthreads();

    float* oR  = out;
    float* oV  = out + Bq;
    float* oLP = out + 2 * Bq;
    float* oA  = oLP + (size_t)Bq * Tt * Nn;
    float* oC  = oA  + (size_t)Bq * Tt;
    float* oP  = oC  + (size_t)Bq * Tt * 2;

    const float4* Wh4 = reinterpret_cast<const float4*>(Wh);

    for (int t = 0; t < Tt; t++) {
        // ---- P0: gates partials, 2-way k-split (both batches per thread, 8 FMA/LDG)
        {
            float4 a0 = make_float4(0.f, 0.f, 0.f, 0.f);
            float4 a1 = make_float4(0.f, 0.f, 0.f, 0.f);
            int k0 = half * 64;
            #pragma unroll 4
            for (int k = k0; k < k0 + 64; k++) {
                float4 wh = Wh4[k * 128 + jj];
                float h0 = sh_h[0][k], h1 = sh_h[1][k];
                a0.x = fmaf(wh.x, h0, a0.x); a0.y = fmaf(wh.y, h0, a0.y);
                a0.z = fmaf(wh.z, h0, a0.z); a0.w = fmaf(wh.w, h0, a0.w);
                a1.x = fmaf(wh.x, h1, a1.x); a1.y = fmaf(wh.y, h1, a1.y);
                a1.z = fmaf(wh.z, h1, a1.z); a1.w = fmaf(wh.w, h1, a1.w);
            }
            sh_part[half][0][jj] = a0;
            sh_part[half][1][jj] = a1;
        }
        __syncthreads();
        // ---- P1: fused reduce + x@Wi row + LSTM pointwise (thread = (b=half, j=jj))
        {
            int b = half, j = jj;
            const float* p0 = reinterpret_cast<const float*>(&sh_part[0][b][0]);
            const float* p1 = reinterpret_cast<const float*>(&sh_part[1][b][0]);
            const float* xw = (t == 0) ? g_xw0
                : g_xw + ((size_t)(b0 + b) * Nn + sh_act[b]) * 512;
            float gi = xw[j]       + p0[j]       + p1[j]       + bl[j];
            float gf = xw[128 + j] + p0[128 + j] + p1[128 + j] + bl[128 + j];
            float gg = xw[256 + j] + p0[256 + j] + p1[256 + j] + bl[256 + j];
            float go = xw[384 + j] + p0[384 + j] + p1[384 + j] + bl[384 + j];
            float c2 = my_sig(gf) * sh_c[b][j] + my_sig(gi) * my_tanh(gg);
            sh_c[b][j] = c2;
            sh_h[b][j] = my_sig(go) * my_tanh(c2);
        }
        __syncthreads();
        // ---- P3: q = h2 @ Wq_g (4 independent accumulator chains)
        {
            int b = half;
            float q0 = 0.f, q1 = 0.f, q2 = 0.f, q3 = 0.f;
            #pragma unroll 4
            for (int k = 0; k < 128; k += 4) {
                q0 = fmaf(Wqg[(k + 0) * 128 + jj], sh_h[b][k + 0], q0);
                q1 = fmaf(Wqg[(k + 1) * 128 + jj], sh_h[b][k + 1], q1);
                q2 = fmaf(Wqg[(k + 2) * 128 + jj], sh_h[b][k + 2], q2);
                q3 = fmaf(Wqg[(k + 3) * 128 + jj], sh_h[b][k + 3], q3);
            }
            sh_q[b][jj] = (q0 + q1) + (q2 + q3);
        }
        __syncthreads();
        // ---- P4: u = sum tanh(e_g+q)*v_g - mask  (2-row ILP per warp)
        {
            float4 vv = reinterpret_cast<const float4*>(sh_vg)[lane];
            for (int r = wid; r + 8 < Gg * Nn; r += 16) {
                int rB = r + 8;
                int bA = r >= Nn, nA = r - (bA ? Nn : 0);
                int bB = rB >= Nn, nB = rB - (bB ? Nn : 0);
                float4 eA = reinterpret_cast<const float4*>(
                    g_eg + ((size_t)(b0 + bA) * Nn + nA) * 128)[lane];
                float4 eB = reinterpret_cast<const float4*>(
                    g_eg + ((size_t)(b0 + bB) * Nn + nB) * 128)[lane];
                float4 qA = reinterpret_cast<const float4*>(sh_q[bA])[lane];
                float4 qB = reinterpret_cast<const float4*>(sh_q[bB])[lane];
                float sA = my_tanh(eA.x + qA.x) * vv.x;
                sA = fmaf(my_tanh(eA.y + qA.y), vv.y, sA);
                sA = fmaf(my_tanh(eA.z + qA.z), vv.z, sA);
                sA = fmaf(my_tanh(eA.w + qA.w), vv.w, sA);
                float sB = my_tanh(eB.x + qB.x) * vv.x;
                sB = fmaf(my_tanh(eB.y + qB.y), vv.y, sB);
                sB = fmaf(my_tanh(eB.z + qB.z), vv.z, sB);
                sB = fmaf(my_tanh(eB.w + qB.w), vv.w, sB);
                #pragma unroll
                for (int o = 16; o; o >>= 1) {
                    sA += __shfl_xor_sync(FULLMASK, sA, o);
                    sB += __shfl_xor_sync(FULLMASK, sB, o);
                }
                if (lane == 0) {
                    sh_u[bA][nA] = sA - 1e9f * sh_mask[bA][nA];
                    sh_u[bB][nB] = sB - 1e9f * sh_mask[bB][nB];
                }
            }
            if (wid < 4) {   // leftover rows 96..99
                int r = Gg * Nn - 4 + wid;
                int b = r >= Nn, n = r - (b ? Nn : 0);
                float4 e = reinterpret_cast<const float4*>(
                    g_eg + ((size_t)(b0 + b) * Nn + n) * 128)[lane];
                float4 q = reinterpret_cast<const float4*>(sh_q[b])[lane];
                float s = my_tanh(e.x + q.x) * vv.x;
                s = fmaf(my_tanh(e.y + q.y), vv.y, s);
                s = fmaf(my_tanh(e.z + q.z), vv.z, s);
                s = fmaf(my_tanh(e.w + q.w), vv.w, s);
                #pragma unroll
                for (int o = 16; o; o >>= 1) s += __shfl_xor_sync(FULLMASK, s, o);
                if (lane == 0) sh_u[b][n] = s - 1e9f * sh_mask[b][n];
            }
        }
        __syncthreads();
        // ---- P5: softmax(u) -> p (warp b handles batch b)
        if (wid < Gg) {
            int b = wid;
            float l0 = sh_u[b][lane];
            float l1 = (lane < 18) ? sh_u[b][lane + 32] : -1e38f;
            float m = fmaxf(l0, l1);
            #pragma unroll
            for (int o = 16; o; o >>= 1) m = fmaxf(m, __shfl_xor_sync(FULLMASK, m, o));
            float e0 = __expf(l0 - m);
            float e1 = (lane < 18) ? __expf(l1 - m) : 0.f;
            float s = e0 + e1;
            #pragma unroll
            for (int o = 16; o; o >>= 1) s += __shfl_xor_sync(FULLMASK, s, o);
            float inv = __fdividef(1.f, s);
            sh_u[b][lane] = e0 * inv;
            if (lane < 18) sh_u[b][lane + 32] = e1 * inv;
        }
        __syncthreads();
        // ---- P6: glimpse g = p @ e_g -> sh_q (4 accumulators)
        {
            int b = half;
            const float* ep = g_eg + ((size_t)(b0 + b) * Nn) * 128 + jj;
            float g0 = 0.f, g1 = 0.f, g2 = 0.f, g3 = 0.f;
            #pragma unroll 4
            for (int n = 0; n < 48; n += 4) {
                g0 = fmaf(sh_u[b][n + 0], ep[(n + 0) * 128], g0);
                g1 = fmaf(sh_u[b][n + 1], ep[(n + 1) * 128], g1);
                g2 = fmaf(sh_u[b][n + 2], ep[(n + 2) * 128], g2);
                g3 = fmaf(sh_u[b][n + 3], ep[(n + 3) * 128], g3);
            }
            g0 = fmaf(sh_u[b][48], ep[48 * 128], g0);
            g1 = fmaf(sh_u[b][49], ep[49 * 128], g1);
            sh_q[b][jj] = (g0 + g1) + (g2 + g3);
        }
        __syncthreads();
        // ---- P7: q2 = g @ Wq_p (4 accumulators)
        {
            int b = half;
            float q0 = 0.f, q1 = 0.f, q2 = 0.f, q3 = 0.f;
            #pragma unroll 4
            for (int k = 0; k < 128; k += 4) {
                q0 = fmaf(Wqp[(k + 0) * 128 + jj], sh_q[b][k + 0], q0);
                q1 = fmaf(Wqp[(k + 1) * 128 + jj], sh_q[b][k + 1], q1);
                q2 = fmaf(Wqp[(k + 2) * 128 + jj], sh_q[b][k + 2], q2);
                q3 = fmaf(Wqp[(k + 3) * 128 + jj], sh_q[b][k + 3], q3);
            }
            sh_q2[b][jj] = (q0 + q1) + (q2 + q3);
        }
        __syncthreads();
        // ---- P8: logit = 10*tanh(u2) - mask (2-row ILP per warp)
        {
            float4 vv = reinterpret_cast<const float4*>(sh_vp)[lane];
            for (int r = wid; r + 8 < Gg * Nn; r += 16) {
                int rB = r + 8;
                int bA = r >= Nn, nA = r - (bA ? Nn : 0);
                int bB = rB >= Nn, nB = rB - (bB ? Nn : 0);
                float4 eA = reinterpret_cast<const float4*>(
                    g_ep + ((size_t)(b0 + bA) * Nn + nA) * 128)[lane];
                float4 eB = reinterpret_cast<const float4*>(
                    g_ep + ((size_t)(b0 + bB) * Nn + nB) * 128)[lane];
                float4 qA = reinterpret_cast<const float4*>(sh_q2[bA])[lane];
                float4 qB = reinterpret_cast<const float4*>(sh_q2[bB])[lane];
                float sA = my_tanh(eA.x + qA.x) * vv.x;
                sA = fmaf(my_tanh(eA.y + qA.y), vv.y, sA);
                sA = fmaf(my_tanh(eA.z + qA.z), vv.z, sA);
                sA = fmaf(my_tanh(eA.w + qA.w), vv.w, sA);
                float sB = my_tanh(eB.x + qB.x) * vv.x;
                sB = fmaf(my_tanh(eB.y + qB.y), vv.y, sB);
                sB = fmaf(my_tanh(eB.z + qB.z), vv.z, sB);
                sB = fmaf(my_tanh(eB.w + qB.w), vv.w, sB);
                #pragma unroll
                for (int o = 16; o; o >>= 1) {
                    sA += __shfl_xor_sync(FULLMASK, sA, o);
                    sB += __shfl_xor_sync(FULLMASK, sB, o);
                }
                if (lane == 0) {
                    sh_u[bA][nA] = 10.0f * my_tanh(sA) - 1e9f * sh_mask[bA][nA];
                    sh_u[bB][nB] = 10.0f * my_tanh(sB) - 1e9f * sh_mask[bB][nB];
                }
            }
            if (wid < 4) {   // leftover rows 96..99
                int r = Gg * Nn - 4 + wid;
                int b = r >= Nn, n = r - (b ? Nn : 0);
                float4 e = reinterpret_cast<const float4*>(
                    g_ep + ((size_t)(b0 + b) * Nn + n) * 128)[lane];
                float4 q = reinterpret_cast<const float4*>(sh_q2[b])[lane];
                float s = my_tanh(e.x + q.x) * vv.x;
                s = fmaf(my_tanh(e.y + q.y), vv.y, s);
                s = fmaf(my_tanh(e.z + q.z), vv.z, s);
                s = fmaf(my_tanh(e.w + q.w), vv.w, s);
                #pragma unroll
                for (int o = 16; o; o >>= 1) s += __shfl_xor_sync(FULLMASK, s, o);
                if (lane == 0) sh_u[b][n] = 10.0f * my_tanh(s) - 1e9f * sh_mask[b][n];
            }
        }
        __syncthreads();
        // ---- P9: log_softmax / softmax / argmax / outputs / state
        if (wid < Gg) {
            int b = wid; int gb = b0 + b;
            float l0 = sh_u[b][lane];
            float l1 = (lane < 18) ? sh_u[b][lane + 32] : -1e38f;
            float m = fmaxf(l0, l1);
            #pragma unroll
            for (int o = 16; o; o >>= 1) m = fmaxf(m, __shfl_xor_sync(FULLMASK, m, o));
            float e0 = __expf(l0 - m);
            float e1 = (lane < 18) ? __expf(l1 - m) : 0.f;
            float s = e0 + e1;
            #pragma unroll
            for (int o = 16; o; o >>= 1) s += __shfl_xor_sync(FULLMASK, s, o);
            float lgs = logf(s);
            float p0 = e0 / s;
            float p1 = e1 / s;
            size_t base = ((size_t)gb * Tt + t) * Nn;
            oLP[base + lane] = (l0 - m) - lgs;
            oP [base + lane] = p0;
            if (lane < 18) {
                oLP[base + lane + 32] = (l1 - m) - lgs;
                oP [base + lane + 32] = p1;
            }
            float bv = p0; int bi = lane;
            if (lane < 18 && p1 > bv) { bv = p1; bi = lane + 32; }
            #pragma unroll
            for (int o = 16; o; o >>= 1) {
                float ov = __shfl_down_sync(FULLMASK, bv, o);
                int   oi = __shfl_down_sync(FULLMASK, bi, o);
                if (ov > bv || (ov == bv && oi < bi)) { bv = ov; bi = oi; }
            }
            if (lane == 0) {
                int a = bi;
                sh_act[b] = a;
                sh_mask[b][a] = 1.0f;
                oA[(size_t)gb * Tt + t] = (float)a;
                float cx = pnt[((size_t)gb * Nn + a) * 2 + 0];
                float cy = pnt[((size_t)gb * Nn + a) * 2 + 1];
                oC[((size_t)gb * Tt + t) * 2 + 0] = cx;
                oC[((size_t)gb * Tt + t) * 2 + 1] = cy;
                if (t == 0) { sh_fx[b] = cx; sh_fy[b] = cy; }
                else {
                    float dx = cx - sh_px[b], dy = cy - sh_py[b];
                    sh_R[b] += sqrtf(dx * dx + dy * dy + 1e-10f);
                }
                sh_px[b] = cx; sh_py[b] = cy;
            }
        }
        __syncthreads();
    } // t loop

    // ---- R closing edge
    if (tid < Gg) {
        int b = tid; int gb = b0 + b;
        float dx = sh_fx[b] - sh_px[b], dy = sh_fy[b] - sh_py[b];
        oR[gb] = sh_R[b] + sqrtf(dx * dx + dy * dy + 1e-10f);
    }
    // ---- dec_last = context[b, last action]  (reuse sh_h)
    sh_h[half][jj] = g_ctx[((size_t)(b0 + half) * Nn + sh_act[half]) * 128 + jj];
    __syncthreads();
    // ---- critic shortcut: hy = dec_last @ Wref_c (softmax over length-1 enc == 1)
    {
        int b = half;
        float ha = 0.f, hb = 0.f;
        #pragma unroll 4
        for (int k = 0; k < 128; k += 2) {
            ha = fmaf(Wrc[k * 128 + jj],       sh_h[b][k],     ha);
            hb = fmaf(Wrc[(k + 1) * 128 + jj], sh_h[b][k + 1], hb);
        }
        sh_q[b][jj] = ha + hb;
    }
    __syncthreads();
    {
        int b = half;
        float za = 0.f, zb = 0.f;
        #pragma unroll 4
        for (int k = 0; k < 128; k += 2) {
            za = fmaf(W1[k * 128 + jj],       sh_q[b][k],     za);
            zb = fmaf(W1[(k + 1) * 128 + jj], sh_q[b][k + 1], zb);
        }
        sh_q2[b][jj] = fmaxf(za + zb + b1[jj], 0.f);
    }
    __syncthreads();
    if (wid < Gg) {
        int b = wid; int gb = b0 + b;
        float4 zq = reinterpret_cast<const float4*>(sh_q2[b])[lane];
        float4 w2 = reinterpret_cast<const float4*>(W2)[lane];
        float s = zq.x * w2.x + zq.y * w2.y + zq.z * w2.z + zq.w * w2.w;
        #pragma unroll
        for (int o = 16; o; o >>= 1) s += __shfl_xor_sync(FULLMASK, s, o);
        if (lane == 0) oV[gb] = s + b2[0];
    }
}

extern "C" void kernel_launch(void* const* d_in, const int* in_sizes, int n_in,
                              void* d_out, int out_size) {
    const float* pnt  = (const float*)d_in[0];
    const float* Wemb = (const float*)d_in[1];
    const float* bemb = (const float*)d_in[2];
    const float* dini = (const float*)d_in[3];
    const float* Wi   = (const float*)d_in[4];
    const float* Wh   = (const float*)d_in[5];
    const float* bl   = (const float*)d_in[6];
    const float* Wqg  = (const float*)d_in[7];
    const float* Wrg  = (const float*)d_in[8];
    const float* vg   = (const float*)d_in[9];
    const float* Wqp  = (const float*)d_in[10];
    const float* Wrp  = (const float*)d_in[11];
    const float* vp   = (const float*)d_in[12];
    // d_in[13..16]: Wi_c, Wh_c, b_c, Wq_c — dead (softmax over length-1 enc)
    const float* Wrc  = (const float*)d_in[17];
    // d_in[18]: v_c — dead
    const float* W1   = (const float*)d_in[19];
    const float* b1   = (const float*)d_in[20];
    const float* W2   = (const float*)d_in[21];
    const float* b2   = (const float*)d_in[22];

    k_pre<<<(Bq * Nn) / 64 + 1, 512>>>(pnt, Wemb, bemb, Wrg, Wrp, Wi, dini);
    k_main<<<Bq / Gg, 256>>>(pnt, Wh, bl, Wqg, vg, Wqp, vp,
                             Wrc, W1, b1, W2, b2, (float*)d_out);
}

// round 11
// speedup vs baseline: 1.2852x; 1.0899x over previous
#include <cuda_runtime.h>
#include <math.h>
#include <stdint.h>

#define Bq 1024
#define Nn 50
#define Hh 128
#define Tt 50
#define Gg 2
#define FULLMASK 0xffffffffu

// Scratch (allocation-free rule: __device__ globals)
__device__ float g_ctx[Bq * Nn * Hh];
__device__ float g_eg [Bq * Nn * Hh];
__device__ float g_ep [Bq * Nn * Hh];
__device__ float g_xw [(size_t)Bq * Nn * 512];  // context @ Wi
__device__ float g_xw0[512];                    // dec_init @ Wi

__device__ __forceinline__ float my_tanh(float x) {
    float e = __expf(2.0f * x);
    return 1.0f - __fdividef(2.0f, e + 1.0f);
}
__device__ __forceinline__ float my_sig(float x) {
    return __fdividef(1.0f, 1.0f + __expf(-x));
}

// Merged register-blocked GEMM: two weight-column chunks share each sctx load.
__device__ __forceinline__ void pre_gemm2(
    const float* __restrict__ Wa, int LDa, int cola, float* outA, int LDOa,
    const float* __restrict__ Wb, int LDb, int colb, float* outB, int LDOb,
    const float (*sctx)[128], int rbase, int jj, int row0)
{
    float accA[16], accB[16];
    #pragma unroll
    for (int r = 0; r < 16; r++) { accA[r] = 0.f; accB[r] = 0.f; }
    for (int k4 = 0; k4 < 32; k4++) {
        float wa0 = Wa[(4 * k4 + 0) * LDa + cola + jj];
        float wa1 = Wa[(4 * k4 + 1) * LDa + cola + jj];
        float wa2 = Wa[(4 * k4 + 2) * LDa + cola + jj];
        float wa3 = Wa[(4 * k4 + 3) * LDa + cola + jj];
        float wb0 = Wb[(4 * k4 + 0) * LDb + colb + jj];
        float wb1 = Wb[(4 * k4 + 1) * LDb + colb + jj];
        float wb2 = Wb[(4 * k4 + 2) * LDb + colb + jj];
        float wb3 = Wb[(4 * k4 + 3) * LDb + colb + jj];
        #pragma unroll
        for (int r = 0; r < 16; r++) {
            float4 c = reinterpret_cast<const float4*>(&sctx[rbase + r][0])[k4];
            accA[r] = fmaf(wa0, c.x, fmaf(wa1, c.y, fmaf(wa2, c.z, fmaf(wa3, c.w, accA[r]))));
            accB[r] = fmaf(wb0, c.x, fmaf(wb1, c.y, fmaf(wb2, c.z, fmaf(wb3, c.w, accB[r]))));
        }
    }
    #pragma unroll
    for (int r = 0; r < 16; r++) {
        outA[(size_t)(row0 + rbase + r) * LDOa + cola + jj] = accA[r];
        outB[(size_t)(row0 + rbase + r) * LDOb + colb + jj] = accB[r];
    }
}

// ---------------- Phase A: context, e_g, e_p, ctx@Wi ----------------
__global__ __launch_bounds__(512) void k_pre(
    const float* __restrict__ pnt, const float* __restrict__ Wemb,
    const float* __restrict__ bemb, const float* __restrict__ Wrg,
    const float* __restrict__ Wrp, const float* __restrict__ Wi,
    const float* __restrict__ dini)
{
    if (blockIdx.x == (Bq * Nn) / 64) {
        int j = threadIdx.x;
        float s = 0.f;
        #pragma unroll 4
        for (int k = 0; k < 128; k++) s = fmaf(dini[k], Wi[k * 512 + j], s);
        g_xw0[j] = s;
        return;
    }
    __shared__ __align__(16) float sctx[64][128];
    int row0 = blockIdx.x * 64;
    int tid = threadIdx.x;
    for (int i = tid; i < 64 * 128; i += 512) {
        int r = i >> 7, h = i & 127;
        int row = row0 + r;
        float px = pnt[row * 2 + 0], py = pnt[row * 2 + 1];
        float v = fmaf(px, Wemb[h], fmaf(py, Wemb[128 + h], bemb[h]));
        sctx[r][h] = v;
        g_ctx[(size_t)row * 128 + h] = v;
    }
    __syncthreads();
    int jj = tid & 127;
    int quarter = tid >> 7;
    int rbase = quarter * 16;

    pre_gemm2(Wrg, 128, 0,   g_eg, 128,  Wrp, 128, 0,   g_ep, 128, sctx, rbase, jj, row0);
    pre_gemm2(Wi,  512, 0,   g_xw, 512,  Wi,  512, 128, g_xw, 512, sctx, rbase, jj, row0);
    pre_gemm2(Wi,  512, 256, g_xw, 512,  Wi,  512, 384, g_xw, 512, sctx, rbase, jj, row0);
}

// ---------------- Phase B+C: full T-loop, 4 CTAs/SM ----------------
__global__ __launch_bounds__(256, 4) void k_main(
    const float* __restrict__ pnt, const float* __restrict__ Wh,
    const float* __restrict__ bl,
    const float* __restrict__ Wqg, const float* __restrict__ vg,
    const float* __restrict__ Wqp, const float* __restrict__ vp,
    const float* __restrict__ Wrc, const float* __restrict__ W1,
    const float* __restrict__ b1, const float* __restrict__ W2,
    const float* __restrict__ b2, float* __restrict__ out)
{
    int b0 = blockIdx.x * Gg;
    int tid = threadIdx.x;
    int lane = tid & 31, wid = tid >> 5;   // 8 warps
    int jj = tid & 127;
    int half = tid >> 7;                   // 0..1 : k-half (gates) / batch id (others)

    __shared__ __align__(16) float4 sh_part[2][Gg][128];        // 8 KB gates partials
    __shared__ __align__(16) float sh_h[Gg][128], sh_c[Gg][128];
    __shared__ __align__(16) float sh_q[Gg][128], sh_q2[Gg][128];
    __shared__ float sh_u[Gg][52], sh_mask[Gg][52];
    __shared__ __align__(16) float sh_vg[128], sh_vp[128];
    __shared__ int   sh_act[Gg];
    __shared__ float sh_px[Gg], sh_py[Gg], sh_fx[Gg], sh_fy[Gg], sh_R[Gg];

    {   // init (256 threads == Gg*128 exactly)
        sh_h[half][jj] = 0.f; sh_c[half][jj] = 0.f;
        if (tid < Gg * 52) sh_mask[tid / 52][tid % 52] = 0.f;
        if (tid < 128) { sh_vg[tid] = vg[tid]; sh_vp[tid] = vp[tid]; }
        if (tid < Gg) sh_R[tid] = 0.f;
    }
    __syncthreads();

    float* oR  = out;
    float* oV  = out + Bq;
    float* oLP = out + 2 * Bq;
    float* oA  = oLP + (size_t)Bq * Tt * Nn;
    float* oC  = oA  + (size_t)Bq * Tt;
    float* oP  = oC  + (size_t)Bq * Tt * 2;

    const float4* Wh4 = reinterpret_cast<const float4*>(Wh);
    // per-warp row ownership for attention phases: rows wid, wid+8, ..., (12-13 rows)
    int nrows = (wid < 4) ? 13 : 12;
    int myr = wid + 8 * lane;                     // lane i -> row index owned by this warp
    bool rvalid = (lane < nrows);
    int myb = myr >= Nn, myn = myr - (myb ? Nn : 0);

    for (int t = 0; t < Tt; t++) {
        // ---- P0: gates partials, 2-way k-split (both batches per thread, 8 FMA/LDG)
        {
            float4 a0 = make_float4(0.f, 0.f, 0.f, 0.f);
            float4 a1 = make_float4(0.f, 0.f, 0.f, 0.f);
            int k0 = half * 64;
            #pragma unroll 4
            for (int k = k0; k < k0 + 64; k++) {
                float4 wh = Wh4[k * 128 + jj];
                float h0 = sh_h[0][k], h1 = sh_h[1][k];
                a0.x = fmaf(wh.x, h0, a0.x); a0.y = fmaf(wh.y, h0, a0.y);
                a0.z = fmaf(wh.z, h0, a0.z); a0.w = fmaf(wh.w, h0, a0.w);
                a1.x = fmaf(wh.x, h1, a1.x); a1.y = fmaf(wh.y, h1, a1.y);
                a1.z = fmaf(wh.z, h1, a1.z); a1.w = fmaf(wh.w, h1, a1.w);
            }
            sh_part[half][0][jj] = a0;
            sh_part[half][1][jj] = a1;
        }
        __syncthreads();
        // ---- P1: fused reduce + x@Wi row + LSTM pointwise (thread = (b=half, j=jj))
        {
            int b = half, j = jj;
            const float* p0 = reinterpret_cast<const float*>(&sh_part[0][b][0]);
            const float* p1 = reinterpret_cast<const float*>(&sh_part[1][b][0]);
            const float* xw = (t == 0) ? g_xw0
                : g_xw + ((size_t)(b0 + b) * Nn + sh_act[b]) * 512;
            float gi = xw[j]       + p0[j]       + p1[j]       + bl[j];
            float gf = xw[128 + j] + p0[128 + j] + p1[128 + j] + bl[128 + j];
            float gg = xw[256 + j] + p0[256 + j] + p1[256 + j] + bl[256 + j];
            float go = xw[384 + j] + p0[384 + j] + p1[384 + j] + bl[384 + j];
            float c2 = my_sig(gf) * sh_c[b][j] + my_sig(gi) * my_tanh(gg);
            sh_c[b][j] = c2;
            sh_h[b][j] = my_sig(go) * my_tanh(c2);
        }
        __syncthreads();
        // ---- P3: q = h2 @ Wq_g (4 independent accumulator chains)
        {
            int b = half;
            float q0 = 0.f, q1 = 0.f, q2 = 0.f, q3 = 0.f;
            #pragma unroll 4
            for (int k = 0; k < 128; k += 4) {
                q0 = fmaf(Wqg[(k + 0) * 128 + jj], sh_h[b][k + 0], q0);
                q1 = fmaf(Wqg[(k + 1) * 128 + jj], sh_h[b][k + 1], q1);
                q2 = fmaf(Wqg[(k + 2) * 128 + jj], sh_h[b][k + 2], q2);
                q3 = fmaf(Wqg[(k + 3) * 128 + jj], sh_h[b][k + 3], q3);
            }
            sh_q[b][jj] = (q0 + q1) + (q2 + q3);
        }
        __syncthreads();
        // ---- P4: u = sum tanh(e_g+q)*v_g; masked rows skipped (underflow-exact)
        {
            float4 vv = reinterpret_cast<const float4*>(sh_vg)[lane];
            float mk = rvalid ? sh_mask[myb][myn] : 1.f;
            if (rvalid && mk != 0.f) sh_u[myb][myn] = -1e9f;       // softmax-exact (exp underflows)
            unsigned um = __ballot_sync(FULLMASK, rvalid && mk == 0.f);
            while (um) {
                int i0 = __ffs(um) - 1; um &= um - 1;
                int rA = wid + 8 * i0;
                int bA = rA >= Nn, nA = rA - (bA ? Nn : 0);
                if (um) {
                    int i1 = __ffs(um) - 1; um &= um - 1;
                    int rB = wid + 8 * i1;
                    int bB = rB >= Nn, nB = rB - (bB ? Nn : 0);
                    float4 eA = reinterpret_cast<const float4*>(
                        g_eg + ((size_t)(b0 + bA) * Nn + nA) * 128)[lane];
                    float4 eB = reinterpret_cast<const float4*>(
                        g_eg + ((size_t)(b0 + bB) * Nn + nB) * 128)[lane];
                    float4 qA = reinterpret_cast<const float4*>(sh_q[bA])[lane];
                    float4 qB = reinterpret_cast<const float4*>(sh_q[bB])[lane];
                    float sA = my_tanh(eA.x + qA.x) * vv.x;
                    sA = fmaf(my_tanh(eA.y + qA.y), vv.y, sA);
                    sA = fmaf(my_tanh(eA.z + qA.z), vv.z, sA);
                    sA = fmaf(my_tanh(eA.w + qA.w), vv.w, sA);
                    float sB = my_tanh(eB.x + qB.x) * vv.x;
                    sB = fmaf(my_tanh(eB.y + qB.y), vv.y, sB);
                    sB = fmaf(my_tanh(eB.z + qB.z), vv.z, sB);
                    sB = fmaf(my_tanh(eB.w + qB.w), vv.w, sB);
                    #pragma unroll
                    for (int o = 16; o; o >>= 1) {
                        sA += __shfl_xor_sync(FULLMASK, sA, o);
                        sB += __shfl_xor_sync(FULLMASK, sB, o);
                    }
                    if (lane == 0) { sh_u[bA][nA] = sA; sh_u[bB][nB] = sB; }
                } else {
                    float4 e = reinterpret_cast<const float4*>(
                        g_eg + ((size_t)(b0 + bA) * Nn + nA) * 128)[lane];
                    float4 q = reinterpret_cast<const float4*>(sh_q[bA])[lane];
                    float s = my_tanh(e.x + q.x) * vv.x;
                    s = fmaf(my_tanh(e.y + q.y), vv.y, s);
                    s = fmaf(my_tanh(e.z + q.z), vv.z, s);
                    s = fmaf(my_tanh(e.w + q.w), vv.w, s);
                    #pragma unroll
                    for (int o = 16; o; o >>= 1) s += __shfl_xor_sync(FULLMASK, s, o);
                    if (lane == 0) sh_u[bA][nA] = s;
                }
            }
        }
        __syncthreads();
        // ---- P5: softmax(u) -> p (warp b handles batch b)
        if (wid < Gg) {
            int b = wid;
            float l0 = sh_u[b][lane];
            float l1 = (lane < 18) ? sh_u[b][lane + 32] : -1e38f;
            float m = fmaxf(l0, l1);
            #pragma unroll
            for (int o = 16; o; o >>= 1) m = fmaxf(m, __shfl_xor_sync(FULLMASK, m, o));
            float e0 = __expf(l0 - m);
            float e1 = (lane < 18) ? __expf(l1 - m) : 0.f;
            float s = e0 + e1;
            #pragma unroll
            for (int o = 16; o; o >>= 1) s += __shfl_xor_sync(FULLMASK, s, o);
            float inv = __fdividef(1.f, s);
            sh_u[b][lane] = e0 * inv;
            if (lane < 18) sh_u[b][lane + 32] = e1 * inv;
        }
        __syncthreads();
        // ---- P6: glimpse g = p @ e_g -> sh_q (4 accumulators)
        {
            int b = half;
            const float* ep = g_eg + ((size_t)(b0 + b) * Nn) * 128 + jj;
            float g0 = 0.f, g1 = 0.f, g2 = 0.f, g3 = 0.f;
            #pragma unroll 4
            for (int n = 0; n < 48; n += 4) {
                g0 = fmaf(sh_u[b][n + 0], ep[(n + 0) * 128], g0);
                g1 = fmaf(sh_u[b][n + 1], ep[(n + 1) * 128], g1);
                g2 = fmaf(sh_u[b][n + 2], ep[(n + 2) * 128], g2);
                g3 = fmaf(sh_u[b][n + 3], ep[(n + 3) * 128], g3);
            }
            g0 = fmaf(sh_u[b][48], ep[48 * 128], g0);
            g1 = fmaf(sh_u[b][49], ep[49 * 128], g1);
            sh_q[b][jj] = (g0 + g1) + (g2 + g3);
        }
        __syncthreads();
        // ---- P7: q2 = g @ Wq_p (4 accumulators)
        {
            int b = half;
            float q0 = 0.f, q1 = 0.f, q2 = 0.f, q3 = 0.f;
            #pragma unroll 4
            for (int k = 0; k < 128; k += 4) {
                q0 = fmaf(Wqp[(k + 0) * 128 + jj], sh_q[b][k + 0], q0);
                q1 = fmaf(Wqp[(k + 1) * 128 + jj], sh_q[b][k + 1], q1);
                q2 = fmaf(Wqp[(k + 2) * 128 + jj], sh_q[b][k + 2], q2);
                q3 = fmaf(Wqp[(k + 3) * 128 + jj], sh_q[b][k + 3], q3);
            }
            sh_q2[b][jj] = (q0 + q1) + (q2 + q3);
        }
        __syncthreads();
        // ---- P8: logit = 10*tanh(u2) - mask; masked rows -> -1e9 (1e-8 rel on oLP)
        {
            float4 vv = reinterpret_cast<const float4*>(sh_vp)[lane];
            float mk = rvalid ? sh_mask[myb][myn] : 1.f;
            if (rvalid && mk != 0.f) sh_u[myb][myn] = -1e9f;
            unsigned um = __ballot_sync(FULLMASK, rvalid && mk == 0.f);
            while (um) {
                int i0 = __ffs(um) - 1; um &= um - 1;
                int rA = wid + 8 * i0;
                int bA = rA >= Nn, nA = rA - (bA ? Nn : 0);
                if (um) {
                    int i1 = __ffs(um) - 1; um &= um - 1;
                    int rB = wid + 8 * i1;
                    int bB = rB >= Nn, nB = rB - (bB ? Nn : 0);
                    float4 eA = reinterpret_cast<const float4*>(
                        g_ep + ((size_t)(b0 + bA) * Nn + nA) * 128)[lane];
                    float4 eB = reinterpret_cast<const float4*>(
                        g_ep + ((size_t)(b0 + bB) * Nn + nB) * 128)[lane];
                    float4 qA = reinterpret_cast<const float4*>(sh_q2[bA])[lane];
                    float4 qB = reinterpret_cast<const float4*>(sh_q2[bB])[lane];
                    float sA = my_tanh(eA.x + qA.x) * vv.x;
                    sA = fmaf(my_tanh(eA.y + qA.y), vv.y, sA);
                    sA = fmaf(my_tanh(eA.z + qA.z), vv.z, sA);
                    sA = fmaf(my_tanh(eA.w + qA.w), vv.w, sA);
                    float sB = my_tanh(eB.x + qB.x) * vv.x;
                    sB = fmaf(my_tanh(eB.y + qB.y), vv.y, sB);
                    sB = fmaf(my_tanh(eB.z + qB.z), vv.z, sB);
                    sB = fmaf(my_tanh(eB.w + qB.w), vv.w, sB);
                    #pragma unroll
                    for (int o = 16; o; o >>= 1) {
                        sA += __shfl_xor_sync(FULLMASK, sA, o);
                        sB += __shfl_xor_sync(FULLMASK, sB, o);
                    }
                    if (lane == 0) {
                        sh_u[bA][nA] = 10.0f * my_tanh(sA);
                        sh_u[bB][nB] = 10.0f * my_tanh(sB);
                    }
                } else {
                    float4 e = reinterpret_cast<const float4*>(
                        g_ep + ((size_t)(b0 + bA) * Nn + nA) * 128)[lane];
                    float4 q = reinterpret_cast<const float4*>(sh_q2[bA])[lane];
                    float s = my_tanh(e.x + q.x) * vv.x;
                    s = fmaf(my_tanh(e.y + q.y), vv.y, s);
                    s = fmaf(my_tanh(e.z + q.z), vv.z, s);
                    s = fmaf(my_tanh(e.w + q.w), vv.w, s);
                    #pragma unroll
                    for (int o = 16; o; o >>= 1) s += __shfl_xor_sync(FULLMASK, s, o);
                    if (lane == 0) sh_u[bA][nA] = 10.0f * my_tanh(s);
                }
            }
        }
        __syncthreads();
        // ---- P9: log_softmax / softmax / argmax / outputs / state
        if (wid < Gg) {
            int b = wid; int gb = b0 + b;
            float l0 = sh_u[b][lane];
            float l1 = (lane < 18) ? sh_u[b][lane + 32] : -1e38f;
            float m = fmaxf(l0, l1);
            #pragma unroll
            for (int o = 16; o; o >>= 1) m = fmaxf(m, __shfl_xor_sync(FULLMASK, m, o));
            float e0 = __expf(l0 - m);
            float e1 = (lane < 18) ? __expf(l1 - m) : 0.f;
            float s = e0 + e1;
            #pragma unroll
            for (int o = 16; o; o >>= 1) s += __shfl_xor_sync(FULLMASK, s, o);
            float lgs = logf(s);
            float p0 = e0 / s;
            float p1 = e1 / s;
            size_t base = ((size_t)gb * Tt + t) * Nn;
            oLP[base + lane] = (l0 - m) - lgs;
            oP [base + lane] = p0;
            if (lane < 18) {
                oLP[base + lane + 32] = (l1 - m) - lgs;
                oP [base + lane + 32] = p1;
            }
            float bv = p0; int bi = lane;
            if (lane < 18 && p1 > bv) { bv = p1; bi = lane + 32; }
            #pragma unroll
            for (int o = 16; o; o >>= 1) {
                float ov = __shfl_down_sync(FULLMASK, bv, o);
                int   oi = __shfl_down_sync(FULLMASK, bi, o);
                if (ov > bv || (ov == bv && oi < bi)) { bv = ov; bi = oi; }
            }
            if (lane == 0) {
                int a = bi;
                sh_act[b] = a;
                sh_mask[b][a] = 1.0f;
                oA[(size_t)gb * Tt + t] = (float)a;
                float cx = pnt[((size_t)gb * Nn + a) * 2 + 0];
                float cy = pnt[((size_t)gb * Nn + a) * 2 + 1];
                oC[((size_t)gb * Tt + t) * 2 + 0] = cx;
                oC[((size_t)gb * Tt + t) * 2 + 1] = cy;
                if (t == 0) { sh_fx[b] = cx; sh_fy[b] = cy; }
                else {
                    float dx = cx - sh_px[b], dy = cy - sh_py[b];
                    sh_R[b] += sqrtf(dx * dx + dy * dy + 1e-10f);
                }
                sh_px[b] = cx; sh_py[b] = cy;
            }
        }
        __syncthreads();
    } // t loop

    // ---- R closing edge
    if (tid < Gg) {
        int b = tid; int gb = b0 + b;
        float dx = sh_fx[b] - sh_px[b], dy = sh_fy[b] - sh_py[b];
        oR[gb] = sh_R[b] + sqrtf(dx * dx + dy * dy + 1e-10f);
    }
    // ---- dec_last = context[b, last action]  (reuse sh_h)
    sh_h[half][jj] = g_ctx[((size_t)(b0 + half) * Nn + sh_act[half]) * 128 + jj];
    __syncthreads();
    // ---- critic shortcut: hy = dec_last @ Wref_c (softmax over length-1 enc == 1)
    {
        int b = half;
        float ha = 0.f, hb = 0.f;
        #pragma unroll 4
        for (int k = 0; k < 128; k += 2) {
            ha = fmaf(Wrc[k * 128 + jj],       sh_h[b][k],     ha);
            hb = fmaf(Wrc[(k + 1) * 128 + jj], sh_h[b][k + 1], hb);
        }
        sh_q[b][jj] = ha + hb;
    }
    __syncthreads();
    {
        int b = half;
        float za = 0.f, zb = 0.f;
        #pragma unroll 4
        for (int k = 0; k < 128; k += 2) {
            za = fmaf(W1[k * 128 + jj],       sh_q[b][k],     za);
            zb = fmaf(W1[(k + 1) * 128 + jj], sh_q[b][k + 1], zb);
        }
        sh_q2[b][jj] = fmaxf(za + zb + b1[jj], 0.f);
    }
    __syncthreads();
    if (wid < Gg) {
        int b = wid; int gb = b0 + b;
        float4 zq = reinterpret_cast<const float4*>(sh_q2[b])[lane];
        float4 w2 = reinterpret_cast<const float4*>(W2)[lane];
        float s = zq.x * w2.x + zq.y * w2.y + zq.z * w2.z + zq.w * w2.w;
        #pragma unroll
        for (int o = 16; o; o >>= 1) s += __shfl_xor_sync(FULLMASK, s, o);
        if (lane == 0) oV[gb] = s + b2[0];
    }
}

extern "C" void kernel_launch(void* const* d_in, const int* in_sizes, int n_in,
                              void* d_out, int out_size) {
    const float* pnt  = (const float*)d_in[0];
    const float* Wemb = (const float*)d_in[1];
    const float* bemb = (const float*)d_in[2];
    const float* dini = (const float*)d_in[3];
    const float* Wi   = (const float*)d_in[4];
    const float* Wh   = (const float*)d_in[5];
    const float* bl   = (const float*)d_in[6];
    const float* Wqg  = (const float*)d_in[7];
    const float* Wrg  = (const float*)d_in[8];
    const float* vg   = (const float*)d_in[9];
    const float* Wqp  = (const float*)d_in[10];
    const float* Wrp  = (const float*)d_in[11];
    const float* vp   = (const float*)d_in[12];
    // d_in[13..16]: Wi_c, Wh_c, b_c, Wq_c — dead (softmax over length-1 enc)
    const float* Wrc  = (const float*)d_in[17];
    // d_in[18]: v_c — dead
    const float* W1   = (const float*)d_in[19];
    const float* b1   = (const float*)d_in[20];
    const float* W2   = (const float*)d_in[21];
    const float* b2   = (const float*)d_in[22];

    k_pre<<<(Bq * Nn) / 64 + 1, 512>>>(pnt, Wemb, bemb, Wrg, Wrp, Wi, dini);
    k_main<<<Bq / Gg, 256>>>(pnt, Wh, bl, Wqg, vg, Wqp, vp,
                             Wrc, W1, b1, W2, b2, (float*)d_out);
}